// round 16
// baseline (speedup 1.0000x reference)
#include <cuda_runtime.h>
#include <cuda_fp16.h>
#include <math.h>
#include <stdint.h>

#define B_   4
#define N_   1024
#define K_   512
#define H_   8
#define DH_  64
#define HID_ 2048
#define KG_  (3*K_)
#define BN_  (B_*N_)
#define BNK_ (B_*N_*K_)
#define BHN_ (B_*H_*N_)
#define NN_  (N_*N_)
#define QKVW_ (3*K_)

// ---------------- device scratch ----------------
__device__ __half h_gcatT[KG_*K_];
__device__ __half h_wqkvT[QKVW_*K_];
__device__ __half h_w2qkT[2*K_*K_];
__device__ __half h_WoT[K_*K_];
__device__ __half h_W1T[HID_*K_];
__device__ __half h_W2T[K_*HID_];
__device__ __half h_sig[BNK_];
__device__ __half h_ln1[BNK_];
__device__ __half h_a1[BNK_];
__device__ __half h_mug[BNK_];
__device__ __half h_attn[BNK_];
__device__ __half h_ln2[BNK_];
__device__ __half h_hh[BNK_];
__device__ __half h_hid[BN_*HID_];
__device__ __half h_beta[33554432];
__device__ __half h_bm[B_*NN_];
__device__ __half h_Z[BN_*KG_];
__device__ __half h_Qe[BHN_*2*DH_];
__device__ __half h_Ke[BHN_*2*DH_];
__device__ __half h_o[BNK_];
__device__ __half h_qkv16[BN_*QKVW_];
__device__ float g_ln1[BNK_];
__device__ float g_qkv[BN_*QKVW_];
__device__ float g_s2[BN_*2*K_];
__device__ float g_gam[BHN_];
__device__ float g_del[BHN_];
__device__ float g_beta[33554432];
__device__ float g_o[BNK_];
__device__ float g_res[BNK_];
__device__ float g_ln2[BNK_];
__device__ float g_h[BNK_];
__device__ float g_bh[BNK_];

// ---------------- helpers ----------------
__device__ __forceinline__ float warpSum(float v) {
#pragma unroll
    for (int o = 16; o; o >>= 1) v += __shfl_down_sync(0xffffffffu, v, o);
    return v;
}
__device__ __forceinline__ float allMax(float v) {
#pragma unroll
    for (int o = 16; o; o >>= 1) v = fmaxf(v, __shfl_xor_sync(0xffffffffu, v, o));
    return v;
}
__device__ __forceinline__ float allSum(float v) {
#pragma unroll
    for (int o = 16; o; o >>= 1) v += __shfl_xor_sync(0xffffffffu, v, o);
    return v;
}
__device__ __forceinline__ void cpa16(void* s, const void* g) {
    unsigned sa = (unsigned)__cvta_generic_to_shared(s);
    asm volatile("cp.async.cg.shared.global [%0], [%1], 16;" :: "r"(sa), "l"(g));
}
__device__ __forceinline__ float gelu_f(float x) {
    float x3 = x * x * x;
    return 0.5f * x * (1.f + tanhf(0.7978845608028654f * (x + 0.044715f * x3)));
}
#define LDSM4(R, addr) \
    asm volatile("ldmatrix.sync.aligned.m8n8.x4.shared.b16 {%0,%1,%2,%3}, [%4];" \
                 : "=r"((R)[0]), "=r"((R)[1]), "=r"((R)[2]), "=r"((R)[3]) : "r"(addr))
#define LDSM4T(R, addr) \
    asm volatile("ldmatrix.sync.aligned.m8n8.x4.trans.shared.b16 {%0,%1,%2,%3}, [%4];" \
                 : "=r"((R)[0]), "=r"((R)[1]), "=r"((R)[2]), "=r"((R)[3]) : "r"(addr))
#define MMA16816(D, A, B0, B1) \
    asm volatile("mma.sync.aligned.m16n8k16.row.col.f32.f16.f16.f32 " \
                 "{%0,%1,%2,%3}, {%4,%5,%6,%7}, {%8,%9}, {%0,%1,%2,%3};" \
                 : "+f"((D)[0]), "+f"((D)[1]), "+f"((D)[2]), "+f"((D)[3]) \
                 : "r"((A)[0]), "r"((A)[1]), "r"((A)[2]), "r"((A)[3]), "r"(B0), "r"(B1))

// ============ fp16 tensor-core GEMM, BK=64, 3-stage, single barrier per K-tile ============
// BM=128 fixed, 8 warps 4x2, 256 threads, 2 CTA/SM.
// BT=0: B = Bt [Ncols][Kd] K-major.  BT=1: B row-major [Kd][Ncols].
// epi: 0 fp32; 1 gelu->fp16; 2 VFE->fp32+fp16; 3 VFE+final->fp32; 4 fp16; 5 fp32+fp16
template<int BN, int BT>
__global__ __launch_bounds__(256, 2)
void gemm_h(const __half* __restrict__ A, const __half* __restrict__ Bt,
            float* __restrict__ C, __half* __restrict__ C16,
            int Kd, int lda, int ldb, int ldc,
            long long sAo, long long sAi, long long sBo, long long sBi,
            long long sCo, long long sCi, int innerDiv, int causal, int epi,
            const float* __restrict__ bias,
            const float* __restrict__ e_hin,  const float* __restrict__ e_prior,
            const float* __restrict__ e_aux,  const float* __restrict__ e_lr,
            const float* __restrict__ e_res,  const float* __restrict__ e_ln2)
{
    constexpr int BM = 128, LD = 72;
    constexpr int LDB2 = BN + 8;
    constexpr int WNW = (BN == 64) ? 32 : 64;
    constexpr int WNF = WNW / 8;
    extern __shared__ __half hsm[];
    __half* sA = hsm;
    __half* sB = hsm + 3 * BM * LD;

    int z = blockIdx.z;
    int zo = z / innerDiv, zi = z - zo * innerDiv;
    A  += zo * sAo + zi * sAi;
    Bt += zo * sBo + zi * sBi;
    long long coff = zo * sCo + zi * sCi;

    int tid = threadIdx.x;
    int wid = tid >> 5, lane = tid & 31;
    int wm = wid & 3, wn = wid >> 2;
    int row0 = blockIdx.y * BM, col0 = blockIdx.x * BN;
    int gid = lane >> 2, tig = lane & 3;
    int l8 = lane & 7, lm = lane >> 3;
    int aRow = (lm & 1) * 8 + l8, aCol = (lm >> 1) * 8;
    int bRow, bCol;
    if (BT) { bRow = (lm & 1) * 8 + l8; bCol = (lm >> 1) * 8; }
    else    { bRow = (lm >> 1) * 8 + l8; bCol = (lm & 1) * 8; }

    float acc[2][WNF][4];
#pragma unroll
    for (int mi = 0; mi < 2; mi++)
#pragma unroll
        for (int ni = 0; ni < WNF; ni++)
#pragma unroll
            for (int r = 0; r < 4; r++) acc[mi][ni][r] = 0.f;

    int kTiles = Kd / 64;
    if (causal) { int lim = (row0 + BM) / 64; if (lim < kTiles) kTiles = lim; }

    auto loadTile = [&](int t) {
        int buf = t % 3;
        int k0 = t * 64;
        __half* pA = sA + buf * BM * LD;
        __half* pB = sB + buf * BN * LD;
#pragma unroll
        for (int i = tid; i < BM * 8; i += 256) {
            int m = i >> 3, u = i & 7;
            cpa16(&pA[m * LD + u * 8], A + (size_t)(row0 + m) * lda + k0 + u * 8);
        }
        if (BT) {
            constexpr int PER = BN / 8;
#pragma unroll
            for (int i = tid; i < 64 * PER; i += 256) {
                int kk = i / PER, u = i % PER;
                cpa16(&pB[kk * LDB2 + u * 8], Bt + (size_t)(k0 + kk) * ldb + col0 + u * 8);
            }
        } else {
#pragma unroll
            for (int i = tid; i < BN * 8; i += 256) {
                int n = i >> 3, u = i & 7;
                cpa16(&pB[n * LD + u * 8], Bt + (size_t)(col0 + n) * ldb + k0 + u * 8);
            }
        }
        asm volatile("cp.async.commit_group;");
    };

    loadTile(0);
    if (kTiles > 1) loadTile(1);
    else asm volatile("cp.async.commit_group;");

    for (int t = 0; t < kTiles; t++) {
        asm volatile("cp.async.wait_group 1;");
        __syncthreads();
        if (t + 2 < kTiles) loadTile(t + 2);
        else asm volatile("cp.async.commit_group;");
        int buf = t % 3;
        const __half* pA = sA + buf * BM * LD;
        const __half* pB = sB + buf * BN * LD;
#pragma unroll
        for (int ks = 0; ks < 4; ks++) {
            int kb0 = ks * 16;
            uint32_t a[2][4];
#pragma unroll
            for (int mi = 0; mi < 2; mi++) {
                unsigned ad = (unsigned)__cvta_generic_to_shared(
                    &pA[(wm * 32 + mi * 16 + aRow) * LD + kb0 + aCol]);
                LDSM4(a[mi], ad);
            }
#pragma unroll
            for (int ni2 = 0; ni2 < WNF / 2; ni2++) {
                uint32_t bb[4];
                if (BT) {
                    unsigned bd = (unsigned)__cvta_generic_to_shared(
                        &pB[(kb0 + bRow) * LDB2 + wn * WNW + ni2 * 16 + bCol]);
                    LDSM4T(bb, bd);
                } else {
                    unsigned bd = (unsigned)__cvta_generic_to_shared(
                        &pB[(wn * WNW + ni2 * 16 + bRow) * LD + kb0 + bCol]);
                    LDSM4(bb, bd);
                }
#pragma unroll
                for (int mi = 0; mi < 2; mi++) {
                    MMA16816(acc[mi][2 * ni2],     a[mi], bb[0], bb[1]);
                    MMA16816(acc[mi][2 * ni2 + 1], a[mi], bb[2], bb[3]);
                }
            }
        }
    }
    __syncthreads();

    float lrv = (epi == 2 || epi == 3) ? e_lr[0] : 0.f;
    bool w32 = (epi == 0 || epi == 2 || epi == 3 || epi == 5);
    bool w16 = (epi == 1 || epi == 2 || epi == 4 || epi == 5);
#pragma unroll
    for (int mi = 0; mi < 2; mi++) {
#pragma unroll
        for (int ni = 0; ni < WNF; ni++) {
            int cb = col0 + wn * WNW + ni * 8 + 2 * tig;
#pragma unroll
            for (int hf = 0; hf < 2; hf++) {
                int rr = row0 + wm * 32 + mi * 16 + gid + hf * 8;
                float v0 = acc[mi][ni][hf * 2], v1 = acc[mi][ni][hf * 2 + 1];
                long long off = coff + (long long)rr * ldc + cb;
                if (epi == 1) {
                    v0 = gelu_f(v0 + bias[cb]);
                    v1 = gelu_f(v1 + bias[cb + 1]);
                } else if (epi == 2 || epi == 3) {
                    float x0 = v0 + bias[cb], x1 = v1 + bias[cb + 1];
                    float h0 = e_hin[off], h1 = e_hin[off + 1];
                    v0 = h0 + lrv * (x0 - (1e-3f * (h0 - e_prior[off]) + (h0 - e_aux[off])));
                    v1 = h1 + lrv * (x1 - (1e-3f * (h1 - e_prior[off + 1]) + (h1 - e_aux[off + 1])));
                    if (epi == 3) {
                        v0 = e_res[off] + v0 - e_ln2[off];
                        v1 = e_res[off + 1] + v1 - e_ln2[off + 1];
                    }
                }
                if (w32) { float2 f2; f2.x = v0; f2.y = v1; *(float2*)&C[off] = f2; }
                if (w16) { *(__half2*)&C16[off] = __floats2half2_rn(v0, v1); }
            }
        }
    }
}

// ---------------- merged prep kernels ----------------
__global__ void prep_copy_kernel(const float* __restrict__ gen, const float* __restrict__ sig)
{
    int i = blockIdx.x * 256 + threadIdx.x;
    if (i < KG_ * K_) h_gcatT[i] = __float2half_rn(gen[i]);
    else {
        int j = i - KG_ * K_;
        if (j < BNK_) h_sig[j] = __float2half_rn(sig[j]);
    }
}
__global__ void prep_tr_kernel(const float* __restrict__ Wq, const float* __restrict__ Wk,
                               const float* __restrict__ Wv, const float* __restrict__ Wo,
                               const float* __restrict__ W1, const float* __restrict__ W2)
{
    int lb = blockIdx.x;
    const float* src; __half* dst; int R, C, gx, sq = 0;
    if (lb < 1536) {
        int sel = lb >> 8; lb &= 255;
        R = K_; C = K_; gx = 16;
        switch (sel) {
            case 0: src = Wq; dst = h_wqkvT; break;
            case 1: src = Wk; dst = h_wqkvT + K_ * K_; break;
            case 2: src = Wv; dst = h_wqkvT + 2 * K_ * K_; break;
            case 3: src = Wq; dst = h_w2qkT; sq = 1; break;
            case 4: src = Wk; dst = h_w2qkT + K_ * K_; sq = 1; break;
            default: src = Wo; dst = h_WoT; break;
        }
    } else if (lb < 2560) {
        lb -= 1536; src = W1; dst = h_W1T; R = K_; C = HID_; gx = 64;
    } else {
        lb -= 2560; src = W2; dst = h_W2T; R = HID_; C = K_; gx = 16;
    }
    int bx = (lb % gx) * 32, by = (lb / gx) * 32;
    __shared__ float t[32][33];
    int x = bx + threadIdx.x;
#pragma unroll
    for (int i = 0; i < 32; i += 8) {
        int y = by + threadIdx.y + i;
        float v = src[(size_t)y * C + x];
        if (sq) v = v * v;
        t[threadIdx.y + i][threadIdx.x] = v;
    }
    __syncthreads();
    int xo = by + threadIdx.x;
#pragma unroll
    for (int i = 0; i < 32; i += 8) {
        int yo = bx + threadIdx.y + i;
        dst[(size_t)yo * R + xo] = __float2half_rn(t[threadIdx.x][threadIdx.y + i]);
    }
}

// ---------------- layernorm ----------------
__global__ void ln_kernel(const float* __restrict__ x, const float* __restrict__ gw,
                          const float* __restrict__ bw, float* __restrict__ y,
                          __half* __restrict__ yh)
{
    int bn = blockIdx.x;
    const float* xr = x + (long long)bn * K_;
    int t = threadIdx.x;
    float v0 = xr[t], v1 = xr[t + 256];
    __shared__ float red[8];
    __shared__ float s_mean, s_rstd;
    int lane = t & 31, w = t >> 5;
    float s = warpSum(v0 + v1);
    if (lane == 0) red[w] = s;
    __syncthreads();
    if (t == 0) {
        float tot = 0.f;
        for (int i = 0; i < 8; i++) tot += red[i];
        s_mean = tot * (1.f / 512.f);
    }
    __syncthreads();
    float m = s_mean;
    float d0 = v0 - m, d1 = v1 - m;
    float s2 = warpSum(d0 * d0 + d1 * d1);
    if (lane == 0) red[w] = s2;
    __syncthreads();
    if (t == 0) {
        float tot = 0.f;
        for (int i = 0; i < 8; i++) tot += red[i];
        s_rstd = rsqrtf(tot * (1.f / 512.f) + 1e-5f);
    }
    __syncthreads();
    float r = s_rstd;
    float o0 = d0 * r * gw[t] + bw[t];
    float o1 = d1 * r * gw[t + 256] + bw[t + 256];
    long long base = (long long)bn * K_;
    if (y) { y[base + t] = o0; y[base + t + 256] = o1; }
    if (yh) {
        yh[base + t] = __float2half_rn(o0);
        yh[base + t + 256] = __float2half_rn(o1);
    }
}

// ---------------- transport combines (fp16 Z) ----------------
__global__ void combine1_kernel(const float* __restrict__ phi, float sign)
{
    int i = blockIdx.x * 256 + threadIdx.x;
    if (i >= BNK_) return;
    int bn = i >> 9, k = i & (K_ - 1);
    const float* pp = phi + bn * 3;
    const __half* z = h_Z + (long long)bn * KG_;
    float v = sign * (pp[0] * __half2float(z[k]) + pp[1] * __half2float(z[K_ + k])
                    + pp[2] * __half2float(z[2 * K_ + k]));
    h_a1[i] = __float2half_rn(v);
}
__global__ void combine2_kernel(const float* __restrict__ phi, float sign,
                                const float* __restrict__ xbase,
                                const float* __restrict__ resid,
                                float* __restrict__ out32, __half* __restrict__ out16)
{
    int i = blockIdx.x * 256 + threadIdx.x;
    if (i >= BNK_) return;
    int bn = i >> 9, k = i & (K_ - 1);
    const float* pp = phi + bn * 3;
    const __half* z = h_Z + (long long)bn * KG_;
    float c = sign * (pp[0] * __half2float(z[k]) + pp[1] * __half2float(z[K_ + k])
                    + pp[2] * __half2float(z[2 * K_ + k]));
    float r = xbase[i] + __half2float(h_a1[i]) + 0.5f * c;
    if (resid) r += resid[i];
    if (out32) out32[i] = r;
    if (out16) out16[i] = __float2half_rn(r);
}

// ---------------- fused attention prep -> fp16 Qe/Ke + gamma/delta ----------------
__global__ void prep_attn_gamdel_kernel()
{
    int bn = blockIdx.x;
    int b = bn >> 10, n = bn & (N_ - 1);
    int t = threadIdx.x;
    int lane = t & 31;
    __shared__ float sacc[3][H_];
    if (t < 3 * H_) ((float*)sacc)[t] = 0.f;
    __syncthreads();
#pragma unroll
    for (int half = 0; half < 2; half++) {
        int k = t + half * 256;
        long long s2b = (long long)bn * (2 * K_);
        long long qb  = (long long)bn * QKVW_;
        float sqraw = g_s2[s2b + k] + 1e-8f;
        float inv = 1.f / sqraw;
        float q = g_qkv[qb + k];
        float sk = g_s2[s2b + K_ + k] + 1e-8f;
        float kv = g_qkv[qb + K_ + k];
        int h = k >> 6, d = k & 63;
        size_t qe = (((size_t)(b * H_ + h)) * N_ + n) * 128 + d;
        h_Qe[qe]      = __float2half_rn(-0.5f * inv);
        h_Qe[qe + 64] = __float2half_rn(q * inv);
        h_Ke[qe]      = __float2half_rn(sk + kv * kv);
        h_Ke[qe + 64] = __float2half_rn(kv);
        float qq  = q * q * inv;
        float lsq = logf(sqraw);
        float lsk = logf(sk);
        qq = warpSum(qq); lsq = warpSum(lsq); lsk = warpSum(lsk);
        if (lane == 0) {
            atomicAdd(&sacc[0][h], qq);
            atomicAdd(&sacc[1][h], lsq);
            atomicAdd(&sacc[2][h], lsk);
        }
    }
    __syncthreads();
    if (t < H_) {
        int idx = ((b * H_ + t) * N_) + n;
        g_gam[idx] = -0.5f * (sacc[0][t] - (float)DH_ + sacc[1][t]);
        g_del[idx] = 0.5f * sacc[2][t];
    }
}

// ---------------- KL score: fp16 mma + ldmatrix, 64x64 tiles, K=128 ----------------
__global__ __launch_bounds__(256) void score_kernel()
{
    int bh = blockIdx.z;
    int i0 = blockIdx.y * 64, j0 = blockIdx.x * 64;
    if (j0 > i0) return;
    constexpr int LD = 136;
    __shared__ __half Qs[64 * LD];
    __shared__ __half Ks[64 * LD];
    int tid = threadIdx.x;
    int wid = tid >> 5, lane = tid & 31;
    int wm = wid & 3, wn = wid >> 2;
    int gid = lane >> 2, tig = lane & 3;
    int l8 = lane & 7, lm = lane >> 3;
    int aRow = (lm & 1) * 8 + l8, aCol = (lm >> 1) * 8;
    int bRow = (lm >> 1) * 8 + l8, bCol = (lm & 1) * 8;

    const __half* Qsrc = h_Qe + (((size_t)bh) * N_ + i0) * 128;
    const __half* Ksrc = h_Ke + (((size_t)bh) * N_ + j0) * 128;
    for (int i = tid; i < 1024; i += 256) {
        int r = i >> 4, u = (i & 15) * 8;
        cpa16(&Qs[r * LD + u], Qsrc + (size_t)r * 128 + u);
        cpa16(&Ks[r * LD + u], Ksrc + (size_t)r * 128 + u);
    }
    asm volatile("cp.async.commit_group;");
    asm volatile("cp.async.wait_group 0;");
    __syncthreads();

    float acc[4][4] = {};
#pragma unroll
    for (int ks = 0; ks < 8; ks++) {
        int kb0 = ks * 16;
        uint32_t a[4];
        unsigned ad = (unsigned)__cvta_generic_to_shared(
            &Qs[(wm * 16 + aRow) * LD + kb0 + aCol]);
        LDSM4(a, ad);
#pragma unroll
        for (int ni2 = 0; ni2 < 2; ni2++) {
            uint32_t bb[4];
            unsigned bd = (unsigned)__cvta_generic_to_shared(
                &Ks[(wn * 32 + ni2 * 16 + bRow) * LD + kb0 + bCol]);
            LDSM4(bb, bd);
            MMA16816(acc[2 * ni2],     a, bb[0], bb[1]);
            MMA16816(acc[2 * ni2 + 1], a, bb[2], bb[3]);
        }
    }

    long long gdb = (long long)bh * N_;
#pragma unroll
    for (int hf = 0; hf < 2; hf++) {
        int i = i0 + wm * 16 + gid + hf * 8;
        float gv = g_gam[gdb + i];
#pragma unroll
        for (int ni = 0; ni < 4; ni++) {
            int j = j0 + wn * 32 + ni * 8 + 2 * tig;
            float2 o;
            o.x = acc[ni][hf * 2 + 0] + gv + g_del[gdb + j];
            o.y = acc[ni][hf * 2 + 1] + gv + g_del[gdb + j + 1];
            *(float2*)&g_beta[(gdb + i) * N_ + j] = o;
        }
    }
}

// ---------------- softmax: 1 warp per (head,row) + fused beta_m ----------------
__global__ __launch_bounds__(256) void softmax_bm_kernel()
{
    int bi = blockIdx.x;
    int b = bi >> 10, i = bi & (N_ - 1);
    int Jmax = ((i >> 7) + 1) << 7;
    int tid = threadIdx.x;
    int w = tid >> 5, lane = tid & 31;
    __shared__ float bmbuf[H_][N_];

    long long rowoff = (((long long)(b * H_ + w)) * N_ + i) * N_;
    const float* p = g_beta + rowoff;
    __half* ph = h_beta + rowoff;

    float ev[32];
    float m = -1e30f;
#pragma unroll
    for (int jj = 0; jj < 32; jj++) {
        int j = lane + jj * 32;
        float v = (j <= i) ? p[j] : -1e30f;
        ev[jj] = v;
        m = fmaxf(m, v);
    }
    m = allMax(m);
    float s = 0.f;
#pragma unroll
    for (int jj = 0; jj < 32; jj++) {
        ev[jj] = (lane + jj * 32 <= i) ? expf(ev[jj] - m) : 0.f;
        s += ev[jj];
    }
    s = allSum(s);
    float inv = 1.f / s;
#pragma unroll
    for (int jj = 0; jj < 32; jj++) {
        int j = lane + jj * 32;
        if (j < Jmax) {
            float v = ev[jj] * inv;
            ph[j] = __float2half_rn(v);
            bmbuf[w][j] = v;
        }
    }
    __syncthreads();
    __half* bm = h_bm + ((long long)b * N_ + i) * N_;
    for (int j = tid; j < Jmax; j += 256) {
        float t = 0.f;
#pragma unroll
        for (int h = 0; h < H_; h++) t += bmbuf[h][j];
        bm[j] = __float2half_rn(t * 0.125f);
    }
}

// ---------------- host ----------------
#define SM128 (3 * (128 * 72 + 128 * 72) * 2)   // 110592
#define SM64  (3 * (128 * 72 + 64 * 72) * 2)    // 82944
static inline void launch_gh(cudaStream_t st,
                             const __half* A, const __half* Bt, float* C, __half* C16,
                             int M, int Ncols, int Kd, int lda, int ldb, int ldc,
                             long long sAo, long long sAi, long long sBo, long long sBi,
                             long long sCo, long long sCi, int innerDiv, int batch,
                             int causal, int epi, int btrans, int bn64 = 0,
                             const float* bias = nullptr,
                             const float* e_hin = nullptr, const float* e_prior = nullptr,
                             const float* e_aux = nullptr, const float* e_lr = nullptr,
                             const float* e_res = nullptr, const float* e_ln2 = nullptr)
{
    if (Ncols % 128 == 0 && !bn64) {
        dim3 g(Ncols / 128, M / 128, batch);
        if (btrans)
            gemm_h<128, 1><<<g, 256, SM128, st>>>(A, Bt, C, C16, Kd, lda, ldb, ldc,
                sAo, sAi, sBo, sBi, sCo, sCi, innerDiv, causal, epi,
                bias, e_hin, e_prior, e_aux, e_lr, e_res, e_ln2);
        else
            gemm_h<128, 0><<<g, 256, SM128, st>>>(A, Bt, C, C16, Kd, lda, ldb, ldc,
                sAo, sAi, sBo, sBi, sCo, sCi, innerDiv, causal, epi,
                bias, e_hin, e_prior, e_aux, e_lr, e_res, e_ln2);
    } else {
        dim3 g(Ncols / 64, M / 128, batch);
        if (btrans)
            gemm_h<64, 1><<<g, 256, SM64, st>>>(A, Bt, C, C16, Kd, lda, ldb, ldc,
                sAo, sAi, sBo, sBi, sCo, sCi, innerDiv, causal, epi,
                bias, e_hin, e_prior, e_aux, e_lr, e_res, e_ln2);
        else
            gemm_h<64, 0><<<g, 256, SM64, st>>>(A, Bt, C, C16, Kd, lda, ldb, ldc,
                sAo, sAi, sBo, sBi, sCo, sCi, innerDiv, causal, epi,
                bias, e_hin, e_prior, e_aux, e_lr, e_res, e_ln2);
    }
}

extern "C" void kernel_launch(void* const* d_in, const int* in_sizes, int n_in,
                              void* d_out, int out_size)
{
    const float* mu_q     = (const float*)d_in[0];
    const float* sigma_q  = (const float*)d_in[1];
    const float* phi      = (const float*)d_in[2];
    const float* gen      = (const float*)d_in[3];
    const float* mu_prior = (const float*)d_in[5];
    const float* Wq  = (const float*)d_in[6];
    const float* Wk  = (const float*)d_in[7];
    const float* Wv  = (const float*)d_in[8];
    const float* Wo  = (const float*)d_in[9];
    const float* g1  = (const float*)d_in[10];
    const float* be1 = (const float*)d_in[11];
    const float* g2  = (const float*)d_in[12];
    const float* be2 = (const float*)d_in[13];
    const float* W1  = (const float*)d_in[14];
    const float* bh1 = (const float*)d_in[15];
    const float* W2  = (const float*)d_in[16];
    const float* bh2 = (const float*)d_in[17];
    const float* lr  = (const float*)d_in[18];

    static int initDone = 0;
    static cudaStream_t s1;
    static cudaEvent_t ev[10];
    if (!initDone) {
        cudaFuncSetAttribute(gemm_h<128, 0>, cudaFuncAttributeMaxDynamicSharedMemorySize, SM128);
        cudaFuncSetAttribute(gemm_h<128, 1>, cudaFuncAttributeMaxDynamicSharedMemorySize, SM128);
        cudaFuncSetAttribute(gemm_h<64, 0>,  cudaFuncAttributeMaxDynamicSharedMemorySize, SM64);
        cudaFuncSetAttribute(gemm_h<64, 1>,  cudaFuncAttributeMaxDynamicSharedMemorySize, SM64);
        cudaStreamCreateWithFlags(&s1, cudaStreamNonBlocking);
        for (int i = 0; i < 10; i++) cudaEventCreateWithFlags(&ev[i], cudaEventDisableTiming);
        initDone = 1;
    }

    void* tp;
#define GETSYMF(var, sym) cudaGetSymbolAddress(&tp, sym); float* var = (float*)tp
#define GETSYMH(var, sym) cudaGetSymbolAddress(&tp, sym); __half* var = (__half*)tp
    GETSYMH(ph_gcatT, h_gcatT); GETSYMH(ph_wqkvT, h_wqkvT); GETSYMH(ph_w2qkT, h_w2qkT);
    GETSYMH(ph_WoT, h_WoT);     GETSYMH(ph_W1T, h_W1T);     GETSYMH(ph_W2T, h_W2T);
    GETSYMH(ph_sig, h_sig);     GETSYMH(ph_ln1, h_ln1);     GETSYMH(ph_a1, h_a1);
    GETSYMH(ph_mug, h_mug);     GETSYMH(ph_attn, h_attn);   GETSYMH(ph_o, h_o);
    GETSYMH(ph_ln2, h_ln2);     GETSYMH(ph_hh, h_hh);       GETSYMH(ph_hid, h_hid);
    GETSYMH(ph_beta, h_beta);   GETSYMH(ph_bm, h_bm);       GETSYMH(ph_Z, h_Z);
    GETSYMH(ph_qkv16, h_qkv16);
    GETSYMF(pg_ln1, g_ln1);     GETSYMF(pg_qkv, g_qkv);     GETSYMF(pg_s2, g_s2);
    GETSYMF(pg_o, g_o);         GETSYMF(pg_res, g_res);     GETSYMF(pg_ln2, g_ln2);
    GETSYMF(pg_h, g_h);         GETSYMF(pg_bh, g_bh);
#undef GETSYMF
#undef GETSYMH

    const int EW = 256;
    const int GB_BNK = BNK_ / EW;
    cudaStream_t s0 = 0;
    float* out = (float*)d_out;

    // ---- fork: side stream does output memcpys + fp16 copies ----
    cudaEventRecord(ev[0], s0);
    cudaStreamWaitEvent(s1, ev[0], 0);
    cudaMemcpyAsync(out + BNK_, sigma_q, (size_t)BNK_ * sizeof(float),
                    cudaMemcpyDeviceToDevice, s1);
    cudaMemcpyAsync(out + 2 * (size_t)BNK_, phi, (size_t)B_ * N_ * 3 * sizeof(float),
                    cudaMemcpyDeviceToDevice, s1);
    prep_copy_kernel<<<(KG_ * K_ + BNK_ + EW - 1) / EW, EW, 0, s1>>>(gen, sigma_q);
    cudaEventRecord(ev[1], s1);

    prep_tr_kernel<<<3584, dim3(32, 8), 0, s0>>>(Wq, Wk, Wv, Wo, W1, W2);
    ln_kernel<<<BN_, 256, 0, s0>>>(mu_q, g1, be1, pg_ln1, ph_ln1);
    cudaStreamWaitEvent(s0, ev[1], 0);

    // ---- attention sublayer ----
    launch_gh(s0, ph_ln1, ph_gcatT, nullptr, ph_Z, BN_, KG_, K_, K_, K_, KG_,
              0,0,0,0,0,0, 1, 1, 0, 4, 0);
    combine1_kernel<<<GB_BNK, EW, 0, s0>>>(phi, 1.f);
    launch_gh(s0, ph_a1, ph_gcatT, nullptr, ph_Z, BN_, KG_, K_, K_, K_, KG_,
              0,0,0,0,0,0, 1, 1, 0, 4, 0);
    combine2_kernel<<<GB_BNK, EW, 0, s0>>>(phi, 1.f, pg_ln1, nullptr, nullptr, ph_mug);

    // fork: sigma^2 GEMM on s1 || QKV on s0
    cudaEventRecord(ev[2], s0);
    cudaStreamWaitEvent(s1, ev[2], 0);
    launch_gh(s1, ph_sig, ph_w2qkT, pg_s2, nullptr, BN_, 2 * K_, K_, K_, K_, 2 * K_,
              0,0,0,0,0,0, 1, 1, 0, 0, 0);
    cudaEventRecord(ev[3], s1);
    launch_gh(s0, ph_mug, ph_wqkvT, pg_qkv, ph_qkv16, BN_, QKVW_, K_, K_, K_, QKVW_,
              0,0,0,0,0,0, 1, 1, 0, 5, 0);
    cudaStreamWaitEvent(s0, ev[3], 0);

    prep_attn_gamdel_kernel<<<BN_, 256, 0, s0>>>();
    score_kernel<<<dim3(N_ / 64, N_ / 64, B_ * H_), 256, 0, s0>>>();
    softmax_bm_kernel<<<BN_, 256, 0, s0>>>();

    launch_gh(s0, ph_beta, ph_qkv16 + 2 * K_, nullptr, ph_attn, N_, DH_, N_, N_, QKVW_, K_,
              8LL * NN_, (long long)NN_,
              (long long)N_ * QKVW_, 64,
              (long long)N_ * K_, 64, H_, B_ * H_, 1, 4, 1);

    // Wo: N=512 sub-wave -> BN=64 (256 blocks)
    launch_gh(s0, ph_attn, ph_WoT, pg_o, ph_o, BN_, K_, K_, K_, K_, K_,
              0,0,0,0,0,0, 1, 1, 0, 5, 0, 1);
    launch_gh(s0, ph_o, ph_gcatT, nullptr, ph_Z, BN_, KG_, K_, K_, K_, KG_,
              0,0,0,0,0,0, 1, 1, 0, 4, 0);
    combine1_kernel<<<GB_BNK, EW, 0, s0>>>(phi, -1.f);
    launch_gh(s0, ph_a1, ph_gcatT, nullptr, ph_Z, BN_, KG_, K_, K_, K_, KG_,
              0,0,0,0,0,0, 1, 1, 0, 4, 0);
    combine2_kernel<<<GB_BNK, EW, 0, s0>>>(phi, -1.f, pg_o, mu_q, pg_res, nullptr);

    // ---- FFN sublayer ----
    ln_kernel<<<BN_, 256, 0, s0>>>(pg_res, g2, be2, pg_ln2, ph_ln2);

    // iteration 1: fork bm (BN=64) on s1 || W1 on s0
    cudaEventRecord(ev[4], s0);
    cudaStreamWaitEvent(s1, ev[4], 0);
    launch_gh(s1, ph_bm, ph_ln2, pg_bh, nullptr, N_, K_, N_, N_, K_, K_,
              (long long)NN_, 0, (long long)N_ * K_, 0, (long long)N_ * K_, 0,
              1, B_, 1, 0, 1, 1);
    cudaEventRecord(ev[5], s1);
    launch_gh(s0, ph_ln2, ph_W1T, nullptr, ph_hid, BN_, HID_, K_, K_, K_, HID_,
              0,0,0,0,0,0, 1, 1, 0, 1, 0, 0, bh1);
    cudaStreamWaitEvent(s0, ev[5], 0);
    // W2: N=512 sub-wave -> BN=64 (256 blocks)
    launch_gh(s0, ph_hid, ph_W2T, pg_h, ph_hh, BN_, K_, HID_, HID_, HID_, K_,
              0,0,0,0,0,0, 1, 1, 0, 2, 0, 1, bh2, pg_ln2, mu_prior, pg_bh, lr);

    // iteration 2: fork bm (BN=64) on s1 || W1 on s0
    cudaEventRecord(ev[6], s0);
    cudaStreamWaitEvent(s1, ev[6], 0);
    launch_gh(s1, ph_bm, ph_hh, pg_bh, nullptr, N_, K_, N_, N_, K_, K_,
              (long long)NN_, 0, (long long)N_ * K_, 0, (long long)N_ * K_, 0,
              1, B_, 1, 0, 1, 1);
    cudaEventRecord(ev[7], s1);
    launch_gh(s0, ph_hh, ph_W1T, nullptr, ph_hid, BN_, HID_, K_, K_, K_, HID_,
              0,0,0,0,0,0, 1, 1, 0, 1, 0, 0, bh1);
    cudaStreamWaitEvent(s0, ev[7], 0);
    launch_gh(s0, ph_hid, ph_W2T, out, nullptr, BN_, K_, HID_, HID_, HID_, K_,
              0,0,0,0,0,0, 1, 1, 0, 3, 0, 1, bh2, pg_h, mu_prior, pg_bh, lr, pg_res, pg_ln2);
}

// round 17
// speedup vs baseline: 1.0203x; 1.0203x over previous
#include <cuda_runtime.h>
#include <cuda_fp16.h>
#include <math.h>
#include <stdint.h>

#define B_   4
#define N_   1024
#define K_   512
#define H_   8
#define DH_  64
#define HID_ 2048
#define KG_  (3*K_)
#define BN_  (B_*N_)
#define BNK_ (B_*N_*K_)
#define BHN_ (B_*H_*N_)
#define NN_  (N_*N_)
#define QKVW_ (3*K_)

// ---------------- device scratch ----------------
__device__ __half h_gcatT[KG_*K_];
__device__ __half h_wqkvT[QKVW_*K_];
__device__ __half h_w2qkT[2*K_*K_];
__device__ __half h_WoT[K_*K_];
__device__ __half h_W1T[HID_*K_];
__device__ __half h_W2T[K_*HID_];
__device__ __half h_sig[BNK_];
__device__ __half h_ln1[BNK_];
__device__ __half h_a1[BNK_];
__device__ __half h_mug[BNK_];
__device__ __half h_attn[BNK_];
__device__ __half h_ln2[BNK_];
__device__ __half h_hh[BNK_];
__device__ __half h_hid[BN_*HID_];
__device__ __half h_beta[33554432];
__device__ __half h_bm[B_*NN_];
__device__ __half h_Z[BN_*KG_];
__device__ __half h_Qe[BHN_*2*DH_];
__device__ __half h_Ke[BHN_*2*DH_];
__device__ __half h_o[BNK_];
__device__ __half h_qkv16[BN_*QKVW_];
__device__ float g_ln1[BNK_];
__device__ float g_qkv[BN_*QKVW_];
__device__ float g_s2[BN_*2*K_];
__device__ float g_gam[BHN_];
__device__ float g_del[BHN_];
__device__ float g_beta[33554432];
__device__ float g_o[BNK_];
__device__ float g_res[BNK_];
__device__ float g_ln2[BNK_];
__device__ float g_h[BNK_];
__device__ float g_bh[BNK_];

// ---------------- helpers ----------------
__device__ __forceinline__ float warpSum(float v) {
#pragma unroll
    for (int o = 16; o; o >>= 1) v += __shfl_down_sync(0xffffffffu, v, o);
    return v;
}
__device__ __forceinline__ float allMax(float v) {
#pragma unroll
    for (int o = 16; o; o >>= 1) v = fmaxf(v, __shfl_xor_sync(0xffffffffu, v, o));
    return v;
}
__device__ __forceinline__ float allSum(float v) {
#pragma unroll
    for (int o = 16; o; o >>= 1) v += __shfl_xor_sync(0xffffffffu, v, o);
    return v;
}
__device__ __forceinline__ void cpa16(void* s, const void* g) {
    unsigned sa = (unsigned)__cvta_generic_to_shared(s);
    asm volatile("cp.async.cg.shared.global [%0], [%1], 16;" :: "r"(sa), "l"(g));
}
__device__ __forceinline__ float gelu_f(float x) {
    float x3 = x * x * x;
    return 0.5f * x * (1.f + tanhf(0.7978845608028654f * (x + 0.044715f * x3)));
}
#define LDSM4(R, addr) \
    asm volatile("ldmatrix.sync.aligned.m8n8.x4.shared.b16 {%0,%1,%2,%3}, [%4];" \
                 : "=r"((R)[0]), "=r"((R)[1]), "=r"((R)[2]), "=r"((R)[3]) : "r"(addr))
#define LDSM4T(R, addr) \
    asm volatile("ldmatrix.sync.aligned.m8n8.x4.trans.shared.b16 {%0,%1,%2,%3}, [%4];" \
                 : "=r"((R)[0]), "=r"((R)[1]), "=r"((R)[2]), "=r"((R)[3]) : "r"(addr))
#define MMA16816(D, A, B0, B1) \
    asm volatile("mma.sync.aligned.m16n8k16.row.col.f32.f16.f16.f32 " \
                 "{%0,%1,%2,%3}, {%4,%5,%6,%7}, {%8,%9}, {%0,%1,%2,%3};" \
                 : "+f"((D)[0]), "+f"((D)[1]), "+f"((D)[2]), "+f"((D)[3]) \
                 : "r"((A)[0]), "r"((A)[1]), "r"((A)[2]), "r"((A)[3]), "r"(B0), "r"(B1))

// ============ fp16 tensor-core GEMM, BK=64, 3-stage, single barrier per K-tile ============
// BM=128 fixed, 8 warps 4x2, 256 threads, 2 CTA/SM.
// BT=0: B = Bt [Ncols][Kd] K-major.  BT=1: B row-major [Kd][Ncols].
// epi: 0 fp32; 1 gelu->fp16; 2 VFE->fp32+fp16; 3 VFE+final->fp32; 4 fp16; 5 fp32+fp16
template<int BN, int BT>
__global__ __launch_bounds__(256, 2)
void gemm_h(const __half* __restrict__ A, const __half* __restrict__ Bt,
            float* __restrict__ C, __half* __restrict__ C16,
            int Kd, int lda, int ldb, int ldc,
            long long sAo, long long sAi, long long sBo, long long sBi,
            long long sCo, long long sCi, int innerDiv, int causal, int epi,
            const float* __restrict__ bias,
            const float* __restrict__ e_hin,  const float* __restrict__ e_prior,
            const float* __restrict__ e_aux,  const float* __restrict__ e_lr,
            const float* __restrict__ e_res,  const float* __restrict__ e_ln2)
{
    constexpr int BM = 128, LD = 72;
    constexpr int LDB2 = BN + 8;
    constexpr int WNW = (BN == 64) ? 32 : 64;
    constexpr int WNF = WNW / 8;
    extern __shared__ __half hsm[];
    __half* sA = hsm;
    __half* sB = hsm + 3 * BM * LD;

    int z = blockIdx.z;
    int zo = z / innerDiv, zi = z - zo * innerDiv;
    A  += zo * sAo + zi * sAi;
    Bt += zo * sBo + zi * sBi;
    long long coff = zo * sCo + zi * sCi;

    int tid = threadIdx.x;
    int wid = tid >> 5, lane = tid & 31;
    int wm = wid & 3, wn = wid >> 2;
    int row0 = blockIdx.y * BM, col0 = blockIdx.x * BN;
    int gid = lane >> 2, tig = lane & 3;
    int l8 = lane & 7, lm = lane >> 3;
    int aRow = (lm & 1) * 8 + l8, aCol = (lm >> 1) * 8;
    int bRow, bCol;
    if (BT) { bRow = (lm & 1) * 8 + l8; bCol = (lm >> 1) * 8; }
    else    { bRow = (lm >> 1) * 8 + l8; bCol = (lm & 1) * 8; }

    float acc[2][WNF][4];
#pragma unroll
    for (int mi = 0; mi < 2; mi++)
#pragma unroll
        for (int ni = 0; ni < WNF; ni++)
#pragma unroll
            for (int r = 0; r < 4; r++) acc[mi][ni][r] = 0.f;

    int kTiles = Kd / 64;
    if (causal) { int lim = (row0 + BM) / 64; if (lim < kTiles) kTiles = lim; }

    auto loadTile = [&](int t) {
        int buf = t % 3;
        int k0 = t * 64;
        __half* pA = sA + buf * BM * LD;
        __half* pB = sB + buf * BN * LD;
#pragma unroll
        for (int i = tid; i < BM * 8; i += 256) {
            int m = i >> 3, u = i & 7;
            cpa16(&pA[m * LD + u * 8], A + (size_t)(row0 + m) * lda + k0 + u * 8);
        }
        if (BT) {
            constexpr int PER = BN / 8;
#pragma unroll
            for (int i = tid; i < 64 * PER; i += 256) {
                int kk = i / PER, u = i % PER;
                cpa16(&pB[kk * LDB2 + u * 8], Bt + (size_t)(k0 + kk) * ldb + col0 + u * 8);
            }
        } else {
#pragma unroll
            for (int i = tid; i < BN * 8; i += 256) {
                int n = i >> 3, u = i & 7;
                cpa16(&pB[n * LD + u * 8], Bt + (size_t)(col0 + n) * ldb + k0 + u * 8);
            }
        }
        asm volatile("cp.async.commit_group;");
    };

    loadTile(0);
    if (kTiles > 1) loadTile(1);
    else asm volatile("cp.async.commit_group;");

    for (int t = 0; t < kTiles; t++) {
        asm volatile("cp.async.wait_group 1;");
        __syncthreads();
        if (t + 2 < kTiles) loadTile(t + 2);
        else asm volatile("cp.async.commit_group;");
        int buf = t % 3;
        const __half* pA = sA + buf * BM * LD;
        const __half* pB = sB + buf * BN * LD;
#pragma unroll
        for (int ks = 0; ks < 4; ks++) {
            int kb0 = ks * 16;
            uint32_t a[2][4];
#pragma unroll
            for (int mi = 0; mi < 2; mi++) {
                unsigned ad = (unsigned)__cvta_generic_to_shared(
                    &pA[(wm * 32 + mi * 16 + aRow) * LD + kb0 + aCol]);
                LDSM4(a[mi], ad);
            }
#pragma unroll
            for (int ni2 = 0; ni2 < WNF / 2; ni2++) {
                uint32_t bb[4];
                if (BT) {
                    unsigned bd = (unsigned)__cvta_generic_to_shared(
                        &pB[(kb0 + bRow) * LDB2 + wn * WNW + ni2 * 16 + bCol]);
                    LDSM4T(bb, bd);
                } else {
                    unsigned bd = (unsigned)__cvta_generic_to_shared(
                        &pB[(wn * WNW + ni2 * 16 + bRow) * LD + kb0 + bCol]);
                    LDSM4(bb, bd);
                }
#pragma unroll
                for (int mi = 0; mi < 2; mi++) {
                    MMA16816(acc[mi][2 * ni2],     a[mi], bb[0], bb[1]);
                    MMA16816(acc[mi][2 * ni2 + 1], a[mi], bb[2], bb[3]);
                }
            }
        }
    }
    __syncthreads();

    float lrv = (epi == 2 || epi == 3) ? e_lr[0] : 0.f;
    bool w32 = (epi == 0 || epi == 2 || epi == 3 || epi == 5);
    bool w16 = (epi == 1 || epi == 2 || epi == 4 || epi == 5);
#pragma unroll
    for (int mi = 0; mi < 2; mi++) {
#pragma unroll
        for (int ni = 0; ni < WNF; ni++) {
            int cb = col0 + wn * WNW + ni * 8 + 2 * tig;
#pragma unroll
            for (int hf = 0; hf < 2; hf++) {
                int rr = row0 + wm * 32 + mi * 16 + gid + hf * 8;
                float v0 = acc[mi][ni][hf * 2], v1 = acc[mi][ni][hf * 2 + 1];
                long long off = coff + (long long)rr * ldc + cb;
                if (epi == 1) {
                    v0 = gelu_f(v0 + bias[cb]);
                    v1 = gelu_f(v1 + bias[cb + 1]);
                } else if (epi == 2 || epi == 3) {
                    float x0 = v0 + bias[cb], x1 = v1 + bias[cb + 1];
                    float h0 = e_hin[off], h1 = e_hin[off + 1];
                    v0 = h0 + lrv * (x0 - (1e-3f * (h0 - e_prior[off]) + (h0 - e_aux[off])));
                    v1 = h1 + lrv * (x1 - (1e-3f * (h1 - e_prior[off + 1]) + (h1 - e_aux[off + 1])));
                    if (epi == 3) {
                        v0 = e_res[off] + v0 - e_ln2[off];
                        v1 = e_res[off + 1] + v1 - e_ln2[off + 1];
                    }
                }
                if (w32) { float2 f2; f2.x = v0; f2.y = v1; *(float2*)&C[off] = f2; }
                if (w16) { *(__half2*)&C16[off] = __floats2half2_rn(v0, v1); }
            }
        }
    }
}

// ---------------- merged prep kernels ----------------
__global__ void prep_copy_kernel(const float* __restrict__ gen, const float* __restrict__ sig)
{
    int i = blockIdx.x * 256 + threadIdx.x;
    if (i < KG_ * K_) h_gcatT[i] = __float2half_rn(gen[i]);
    else {
        int j = i - KG_ * K_;
        if (j < BNK_) h_sig[j] = __float2half_rn(sig[j]);
    }
}
__global__ void prep_tr_kernel(const float* __restrict__ Wq, const float* __restrict__ Wk,
                               const float* __restrict__ Wv, const float* __restrict__ Wo,
                               const float* __restrict__ W1, const float* __restrict__ W2)
{
    int lb = blockIdx.x;
    const float* src; __half* dst; int R, C, gx, sq = 0;
    if (lb < 1536) {
        int sel = lb >> 8; lb &= 255;
        R = K_; C = K_; gx = 16;
        switch (sel) {
            case 0: src = Wq; dst = h_wqkvT; break;
            case 1: src = Wk; dst = h_wqkvT + K_ * K_; break;
            case 2: src = Wv; dst = h_wqkvT + 2 * K_ * K_; break;
            case 3: src = Wq; dst = h_w2qkT; sq = 1; break;
            case 4: src = Wk; dst = h_w2qkT + K_ * K_; sq = 1; break;
            default: src = Wo; dst = h_WoT; break;
        }
    } else if (lb < 2560) {
        lb -= 1536; src = W1; dst = h_W1T; R = K_; C = HID_; gx = 64;
    } else {
        lb -= 2560; src = W2; dst = h_W2T; R = HID_; C = K_; gx = 16;
    }
    int bx = (lb % gx) * 32, by = (lb / gx) * 32;
    __shared__ float t[32][33];
    int x = bx + threadIdx.x;
#pragma unroll
    for (int i = 0; i < 32; i += 8) {
        int y = by + threadIdx.y + i;
        float v = src[(size_t)y * C + x];
        if (sq) v = v * v;
        t[threadIdx.y + i][threadIdx.x] = v;
    }
    __syncthreads();
    int xo = by + threadIdx.x;
#pragma unroll
    for (int i = 0; i < 32; i += 8) {
        int yo = bx + threadIdx.y + i;
        dst[(size_t)yo * R + xo] = __float2half_rn(t[threadIdx.x][threadIdx.y + i]);
    }
}

// ---------------- layernorm ----------------
__global__ void ln_kernel(const float* __restrict__ x, const float* __restrict__ gw,
                          const float* __restrict__ bw, float* __restrict__ y,
                          __half* __restrict__ yh)
{
    int bn = blockIdx.x;
    const float* xr = x + (long long)bn * K_;
    int t = threadIdx.x;
    float v0 = xr[t], v1 = xr[t + 256];
    __shared__ float red[8];
    __shared__ float s_mean, s_rstd;
    int lane = t & 31, w = t >> 5;
    float s = warpSum(v0 + v1);
    if (lane == 0) red[w] = s;
    __syncthreads();
    if (t == 0) {
        float tot = 0.f;
        for (int i = 0; i < 8; i++) tot += red[i];
        s_mean = tot * (1.f / 512.f);
    }
    __syncthreads();
    float m = s_mean;
    float d0 = v0 - m, d1 = v1 - m;
    float s2 = warpSum(d0 * d0 + d1 * d1);
    if (lane == 0) red[w] = s2;
    __syncthreads();
    if (t == 0) {
        float tot = 0.f;
        for (int i = 0; i < 8; i++) tot += red[i];
        s_rstd = rsqrtf(tot * (1.f / 512.f) + 1e-5f);
    }
    __syncthreads();
    float r = s_rstd;
    float o0 = d0 * r * gw[t] + bw[t];
    float o1 = d1 * r * gw[t + 256] + bw[t + 256];
    long long base = (long long)bn * K_;
    if (y) { y[base + t] = o0; y[base + t + 256] = o1; }
    if (yh) {
        yh[base + t] = __float2half_rn(o0);
        yh[base + t + 256] = __float2half_rn(o1);
    }
}

// ---------------- transport combines (fp16 Z, half2-vectorized) ----------------
__global__ void combine1_kernel(const float* __restrict__ phi, float sign)
{
    int i2 = blockIdx.x * 256 + threadIdx.x;
    if (i2 >= BNK_ / 2) return;
    int i = i2 * 2;
    int bn = i >> 9, k = i & (K_ - 1);
    const float* pp = phi + bn * 3;
    const __half* z = h_Z + (long long)bn * KG_;
    float2 f0 = __half22float2(*(const __half2*)&z[k]);
    float2 f1 = __half22float2(*(const __half2*)&z[K_ + k]);
    float2 f2 = __half22float2(*(const __half2*)&z[2 * K_ + k]);
    float vx = sign * (pp[0] * f0.x + pp[1] * f1.x + pp[2] * f2.x);
    float vy = sign * (pp[0] * f0.y + pp[1] * f1.y + pp[2] * f2.y);
    *(__half2*)&h_a1[i] = __floats2half2_rn(vx, vy);
}
__global__ void combine2_kernel(const float* __restrict__ phi, float sign,
                                const float* __restrict__ xbase,
                                const float* __restrict__ resid,
                                float* __restrict__ out32, __half* __restrict__ out16)
{
    int i2 = blockIdx.x * 256 + threadIdx.x;
    if (i2 >= BNK_ / 2) return;
    int i = i2 * 2;
    int bn = i >> 9, k = i & (K_ - 1);
    const float* pp = phi + bn * 3;
    const __half* z = h_Z + (long long)bn * KG_;
    float2 f0 = __half22float2(*(const __half2*)&z[k]);
    float2 f1 = __half22float2(*(const __half2*)&z[K_ + k]);
    float2 f2 = __half22float2(*(const __half2*)&z[2 * K_ + k]);
    float cx = sign * (pp[0] * f0.x + pp[1] * f1.x + pp[2] * f2.x);
    float cy = sign * (pp[0] * f0.y + pp[1] * f1.y + pp[2] * f2.y);
    float2 xb = *(const float2*)&xbase[i];
    float2 a1 = __half22float2(*(const __half2*)&h_a1[i]);
    float rx = xb.x + a1.x + 0.5f * cx;
    float ry = xb.y + a1.y + 0.5f * cy;
    if (resid) {
        float2 rs = *(const float2*)&resid[i];
        rx += rs.x; ry += rs.y;
    }
    if (out32) { float2 o; o.x = rx; o.y = ry; *(float2*)&out32[i] = o; }
    if (out16) *(__half2*)&out16[i] = __floats2half2_rn(rx, ry);
}

// ---------------- fused attention prep -> fp16 Qe/Ke + gamma/delta ----------------
__global__ void prep_attn_gamdel_kernel()
{
    int bn = blockIdx.x;
    int b = bn >> 10, n = bn & (N_ - 1);
    int t = threadIdx.x;
    int lane = t & 31;
    __shared__ float sacc[3][H_];
    if (t < 3 * H_) ((float*)sacc)[t] = 0.f;
    __syncthreads();
#pragma unroll
    for (int half = 0; half < 2; half++) {
        int k = t + half * 256;
        long long s2b = (long long)bn * (2 * K_);
        long long qb  = (long long)bn * QKVW_;
        float sqraw = g_s2[s2b + k] + 1e-8f;
        float inv = 1.f / sqraw;
        float q = g_qkv[qb + k];
        float sk = g_s2[s2b + K_ + k] + 1e-8f;
        float kv = g_qkv[qb + K_ + k];
        int h = k >> 6, d = k & 63;
        size_t qe = (((size_t)(b * H_ + h)) * N_ + n) * 128 + d;
        h_Qe[qe]      = __float2half_rn(-0.5f * inv);
        h_Qe[qe + 64] = __float2half_rn(q * inv);
        h_Ke[qe]      = __float2half_rn(sk + kv * kv);
        h_Ke[qe + 64] = __float2half_rn(kv);
        float qq  = q * q * inv;
        float lsq = logf(sqraw);
        float lsk = logf(sk);
        qq = warpSum(qq); lsq = warpSum(lsq); lsk = warpSum(lsk);
        if (lane == 0) {
            atomicAdd(&sacc[0][h], qq);
            atomicAdd(&sacc[1][h], lsq);
            atomicAdd(&sacc[2][h], lsk);
        }
    }
    __syncthreads();
    if (t < H_) {
        int idx = ((b * H_ + t) * N_) + n;
        g_gam[idx] = -0.5f * (sacc[0][t] - (float)DH_ + sacc[1][t]);
        g_del[idx] = 0.5f * sacc[2][t];
    }
}

// ---------------- KL score: fp16 mma + ldmatrix, triangular tile grid ----------------
__global__ __launch_bounds__(256) void score_kernel()
{
    int bh = blockIdx.z;
    // decode lower-triangle tile index (136 tiles for 16x16)
    int tlin = blockIdx.x;
    int ti = (int)((sqrtf(8.f * (float)tlin + 1.f) - 1.f) * 0.5f);
    while ((ti + 1) * (ti + 2) / 2 <= tlin) ti++;
    while (ti * (ti + 1) / 2 > tlin) ti--;
    int tj = tlin - ti * (ti + 1) / 2;
    int i0 = ti * 64, j0 = tj * 64;

    constexpr int LD = 136;
    __shared__ __half Qs[64 * LD];
    __shared__ __half Ks[64 * LD];
    int tid = threadIdx.x;
    int wid = tid >> 5, lane = tid & 31;
    int wm = wid & 3, wn = wid >> 2;
    int gid = lane >> 2, tig = lane & 3;
    int l8 = lane & 7, lm = lane >> 3;
    int aRow = (lm & 1) * 8 + l8, aCol = (lm >> 1) * 8;
    int bRow = (lm >> 1) * 8 + l8, bCol = (lm & 1) * 8;

    const __half* Qsrc = h_Qe + (((size_t)bh) * N_ + i0) * 128;
    const __half* Ksrc = h_Ke + (((size_t)bh) * N_ + j0) * 128;
    for (int i = tid; i < 1024; i += 256) {
        int r = i >> 4, u = (i & 15) * 8;
        cpa16(&Qs[r * LD + u], Qsrc + (size_t)r * 128 + u);
        cpa16(&Ks[r * LD + u], Ksrc + (size_t)r * 128 + u);
    }
    asm volatile("cp.async.commit_group;");
    asm volatile("cp.async.wait_group 0;");
    __syncthreads();

    float acc[4][4] = {};
#pragma unroll
    for (int ks = 0; ks < 8; ks++) {
        int kb0 = ks * 16;
        uint32_t a[4];
        unsigned ad = (unsigned)__cvta_generic_to_shared(
            &Qs[(wm * 16 + aRow) * LD + kb0 + aCol]);
        LDSM4(a, ad);
#pragma unroll
        for (int ni2 = 0; ni2 < 2; ni2++) {
            uint32_t bb[4];
            unsigned bd = (unsigned)__cvta_generic_to_shared(
                &Ks[(wn * 32 + ni2 * 16 + bRow) * LD + kb0 + bCol]);
            LDSM4(bb, bd);
            MMA16816(acc[2 * ni2],     a, bb[0], bb[1]);
            MMA16816(acc[2 * ni2 + 1], a, bb[2], bb[3]);
        }
    }

    long long gdb = (long long)bh * N_;
#pragma unroll
    for (int hf = 0; hf < 2; hf++) {
        int i = i0 + wm * 16 + gid + hf * 8;
        float gv = g_gam[gdb + i];
#pragma unroll
        for (int ni = 0; ni < 4; ni++) {
            int j = j0 + wn * 32 + ni * 8 + 2 * tig;
            float2 o;
            o.x = acc[ni][hf * 2 + 0] + gv + g_del[gdb + j];
            o.y = acc[ni][hf * 2 + 1] + gv + g_del[gdb + j + 1];
            *(float2*)&g_beta[(gdb + i) * N_ + j] = o;
        }
    }
}

// ---------------- softmax: 1 warp per (head,row) + fused beta_m ----------------
__global__ __launch_bounds__(256) void softmax_bm_kernel()
{
    int bi = blockIdx.x;
    int b = bi >> 10, i = bi & (N_ - 1);
    int Jmax = ((i >> 7) + 1) << 7;
    int tid = threadIdx.x;
    int w = tid >> 5, lane = tid & 31;
    __shared__ float bmbuf[H_][N_];

    long long rowoff = (((long long)(b * H_ + w)) * N_ + i) * N_;
    const float* p = g_beta + rowoff;
    __half* ph = h_beta + rowoff;

    float ev[32];
    float m = -1e30f;
#pragma unroll
    for (int jj = 0; jj < 32; jj++) {
        int j = lane + jj * 32;
        float v = (j <= i) ? p[j] : -1e30f;
        ev[jj] = v;
        m = fmaxf(m, v);
    }
    m = allMax(m);
    float s = 0.f;
#pragma unroll
    for (int jj = 0; jj < 32; jj++) {
        ev[jj] = (lane + jj * 32 <= i) ? expf(ev[jj] - m) : 0.f;
        s += ev[jj];
    }
    s = allSum(s);
    float inv = 1.f / s;
#pragma unroll
    for (int jj = 0; jj < 32; jj++) {
        int j = lane + jj * 32;
        if (j < Jmax) {
            float v = ev[jj] * inv;
            ph[j] = __float2half_rn(v);
            bmbuf[w][j] = v;
        }
    }
    __syncthreads();
    __half* bm = h_bm + ((long long)b * N_ + i) * N_;
    for (int j = tid; j < Jmax; j += 256) {
        float t = 0.f;
#pragma unroll
        for (int h = 0; h < H_; h++) t += bmbuf[h][j];
        bm[j] = __float2half_rn(t * 0.125f);
    }
}

// ---------------- host ----------------
#define SM128 (3 * (128 * 72 + 128 * 72) * 2)   // 110592
#define SM64  (3 * (128 * 72 + 64 * 72) * 2)    // 82944
static inline void launch_gh(cudaStream_t st,
                             const __half* A, const __half* Bt, float* C, __half* C16,
                             int M, int Ncols, int Kd, int lda, int ldb, int ldc,
                             long long sAo, long long sAi, long long sBo, long long sBi,
                             long long sCo, long long sCi, int innerDiv, int batch,
                             int causal, int epi, int btrans,
                             const float* bias = nullptr,
                             const float* e_hin = nullptr, const float* e_prior = nullptr,
                             const float* e_aux = nullptr, const float* e_lr = nullptr,
                             const float* e_res = nullptr, const float* e_ln2 = nullptr)
{
    if (Ncols % 128 == 0) {
        dim3 g(Ncols / 128, M / 128, batch);
        if (btrans)
            gemm_h<128, 1><<<g, 256, SM128, st>>>(A, Bt, C, C16, Kd, lda, ldb, ldc,
                sAo, sAi, sBo, sBi, sCo, sCi, innerDiv, causal, epi,
                bias, e_hin, e_prior, e_aux, e_lr, e_res, e_ln2);
        else
            gemm_h<128, 0><<<g, 256, SM128, st>>>(A, Bt, C, C16, Kd, lda, ldb, ldc,
                sAo, sAi, sBo, sBi, sCo, sCi, innerDiv, causal, epi,
                bias, e_hin, e_prior, e_aux, e_lr, e_res, e_ln2);
    } else {
        dim3 g(Ncols / 64, M / 128, batch);
        if (btrans)
            gemm_h<64, 1><<<g, 256, SM64, st>>>(A, Bt, C, C16, Kd, lda, ldb, ldc,
                sAo, sAi, sBo, sBi, sCo, sCi, innerDiv, causal, epi,
                bias, e_hin, e_prior, e_aux, e_lr, e_res, e_ln2);
        else
            gemm_h<64, 0><<<g, 256, SM64, st>>>(A, Bt, C, C16, Kd, lda, ldb, ldc,
                sAo, sAi, sBo, sBi, sCo, sCi, innerDiv, causal, epi,
                bias, e_hin, e_prior, e_aux, e_lr, e_res, e_ln2);
    }
}

extern "C" void kernel_launch(void* const* d_in, const int* in_sizes, int n_in,
                              void* d_out, int out_size)
{
    const float* mu_q     = (const float*)d_in[0];
    const float* sigma_q  = (const float*)d_in[1];
    const float* phi      = (const float*)d_in[2];
    const float* gen      = (const float*)d_in[3];
    const float* mu_prior = (const float*)d_in[5];
    const float* Wq  = (const float*)d_in[6];
    const float* Wk  = (const float*)d_in[7];
    const float* Wv  = (const float*)d_in[8];
    const float* Wo  = (const float*)d_in[9];
    const float* g1  = (const float*)d_in[10];
    const float* be1 = (const float*)d_in[11];
    const float* g2  = (const float*)d_in[12];
    const float* be2 = (const float*)d_in[13];
    const float* W1  = (const float*)d_in[14];
    const float* bh1 = (const float*)d_in[15];
    const float* W2  = (const float*)d_in[16];
    const float* bh2 = (const float*)d_in[17];
    const float* lr  = (const float*)d_in[18];

    static int initDone = 0;
    static cudaStream_t s1;
    static cudaEvent_t ev[10];
    if (!initDone) {
        cudaFuncSetAttribute(gemm_h<128, 0>, cudaFuncAttributeMaxDynamicSharedMemorySize, SM128);
        cudaFuncSetAttribute(gemm_h<128, 1>, cudaFuncAttributeMaxDynamicSharedMemorySize, SM128);
        cudaFuncSetAttribute(gemm_h<64, 0>,  cudaFuncAttributeMaxDynamicSharedMemorySize, SM64);
        cudaFuncSetAttribute(gemm_h<64, 1>,  cudaFuncAttributeMaxDynamicSharedMemorySize, SM64);
        cudaStreamCreateWithFlags(&s1, cudaStreamNonBlocking);
        for (int i = 0; i < 10; i++) cudaEventCreateWithFlags(&ev[i], cudaEventDisableTiming);
        initDone = 1;
    }

    void* tp;
#define GETSYMF(var, sym) cudaGetSymbolAddress(&tp, sym); float* var = (float*)tp
#define GETSYMH(var, sym) cudaGetSymbolAddress(&tp, sym); __half* var = (__half*)tp
    GETSYMH(ph_gcatT, h_gcatT); GETSYMH(ph_wqkvT, h_wqkvT); GETSYMH(ph_w2qkT, h_w2qkT);
    GETSYMH(ph_WoT, h_WoT);     GETSYMH(ph_W1T, h_W1T);     GETSYMH(ph_W2T, h_W2T);
    GETSYMH(ph_sig, h_sig);     GETSYMH(ph_ln1, h_ln1);     GETSYMH(ph_a1, h_a1);
    GETSYMH(ph_mug, h_mug);     GETSYMH(ph_attn, h_attn);   GETSYMH(ph_o, h_o);
    GETSYMH(ph_ln2, h_ln2);     GETSYMH(ph_hh, h_hh);       GETSYMH(ph_hid, h_hid);
    GETSYMH(ph_beta, h_beta);   GETSYMH(ph_bm, h_bm);       GETSYMH(ph_Z, h_Z);
    GETSYMH(ph_qkv16, h_qkv16);
    GETSYMF(pg_ln1, g_ln1);     GETSYMF(pg_qkv, g_qkv);     GETSYMF(pg_s2, g_s2);
    GETSYMF(pg_o, g_o);         GETSYMF(pg_res, g_res);     GETSYMF(pg_ln2, g_ln2);
    GETSYMF(pg_h, g_h);         GETSYMF(pg_bh, g_bh);
#undef GETSYMF
#undef GETSYMH

    const int EW = 256;
    const int GB_V2 = (BNK_ / 2) / EW;   // vectorized combine grid
    cudaStream_t s0 = 0;
    float* out = (float*)d_out;

    // ---- fork: side stream does output memcpys + fp16 copies ----
    cudaEventRecord(ev[0], s0);
    cudaStreamWaitEvent(s1, ev[0], 0);
    cudaMemcpyAsync(out + BNK_, sigma_q, (size_t)BNK_ * sizeof(float),
                    cudaMemcpyDeviceToDevice, s1);
    cudaMemcpyAsync(out + 2 * (size_t)BNK_, phi, (size_t)B_ * N_ * 3 * sizeof(float),
                    cudaMemcpyDeviceToDevice, s1);
    prep_copy_kernel<<<(KG_ * K_ + BNK_ + EW - 1) / EW, EW, 0, s1>>>(gen, sigma_q);
    cudaEventRecord(ev[1], s1);

    prep_tr_kernel<<<3584, dim3(32, 8), 0, s0>>>(Wq, Wk, Wv, Wo, W1, W2);
    ln_kernel<<<BN_, 256, 0, s0>>>(mu_q, g1, be1, pg_ln1, ph_ln1);
    cudaStreamWaitEvent(s0, ev[1], 0);

    // ---- attention sublayer ----
    launch_gh(s0, ph_ln1, ph_gcatT, nullptr, ph_Z, BN_, KG_, K_, K_, K_, KG_,
              0,0,0,0,0,0, 1, 1, 0, 4, 0);
    combine1_kernel<<<GB_V2, EW, 0, s0>>>(phi, 1.f);
    launch_gh(s0, ph_a1, ph_gcatT, nullptr, ph_Z, BN_, KG_, K_, K_, K_, KG_,
              0,0,0,0,0,0, 1, 1, 0, 4, 0);
    combine2_kernel<<<GB_V2, EW, 0, s0>>>(phi, 1.f, pg_ln1, nullptr, nullptr, ph_mug);

    // fork: sigma^2 GEMM on s1 || QKV on s0
    cudaEventRecord(ev[2], s0);
    cudaStreamWaitEvent(s1, ev[2], 0);
    launch_gh(s1, ph_sig, ph_w2qkT, pg_s2, nullptr, BN_, 2 * K_, K_, K_, K_, 2 * K_,
              0,0,0,0,0,0, 1, 1, 0, 0, 0);
    cudaEventRecord(ev[3], s1);
    launch_gh(s0, ph_mug, ph_wqkvT, pg_qkv, ph_qkv16, BN_, QKVW_, K_, K_, K_, QKVW_,
              0,0,0,0,0,0, 1, 1, 0, 5, 0);
    cudaStreamWaitEvent(s0, ev[3], 0);

    prep_attn_gamdel_kernel<<<BN_, 256, 0, s0>>>();
    score_kernel<<<dim3(136, 1, B_ * H_), 256, 0, s0>>>();
    softmax_bm_kernel<<<BN_, 256, 0, s0>>>();

    launch_gh(s0, ph_beta, ph_qkv16 + 2 * K_, nullptr, ph_attn, N_, DH_, N_, N_, QKVW_, K_,
              8LL * NN_, (long long)NN_,
              (long long)N_ * QKVW_, 64,
              (long long)N_ * K_, 64, H_, B_ * H_, 1, 4, 1);

    launch_gh(s0, ph_attn, ph_WoT, pg_o, ph_o, BN_, K_, K_, K_, K_, K_,
              0,0,0,0,0,0, 1, 1, 0, 5, 0);
    launch_gh(s0, ph_o, ph_gcatT, nullptr, ph_Z, BN_, KG_, K_, K_, K_, KG_,
              0,0,0,0,0,0, 1, 1, 0, 4, 0);
    combine1_kernel<<<GB_V2, EW, 0, s0>>>(phi, -1.f);
    launch_gh(s0, ph_a1, ph_gcatT, nullptr, ph_Z, BN_, KG_, K_, K_, K_, KG_,
              0,0,0,0,0,0, 1, 1, 0, 4, 0);
    combine2_kernel<<<GB_V2, EW, 0, s0>>>(phi, -1.f, pg_o, mu_q, pg_res, nullptr);

    // ---- FFN sublayer ----
    ln_kernel<<<BN_, 256, 0, s0>>>(pg_res, g2, be2, pg_ln2, ph_ln2);

    // iteration 1: fork bm on s1 || W1 on s0
    cudaEventRecord(ev[4], s0);
    cudaStreamWaitEvent(s1, ev[4], 0);
    launch_gh(s1, ph_bm, ph_ln2, pg_bh, nullptr, N_, K_, N_, N_, K_, K_,
              (long long)NN_, 0, (long long)N_ * K_, 0, (long long)N_ * K_, 0,
              1, B_, 1, 0, 1);
    cudaEventRecord(ev[5], s1);
    launch_gh(s0, ph_ln2, ph_W1T, nullptr, ph_hid, BN_, HID_, K_, K_, K_, HID_,
              0,0,0,0,0,0, 1, 1, 0, 1, 0, bh1);
    cudaStreamWaitEvent(s0, ev[5], 0);
    launch_gh(s0, ph_hid, ph_W2T, pg_h, ph_hh, BN_, K_, HID_, HID_, HID_, K_,
              0,0,0,0,0,0, 1, 1, 0, 2, 0, bh2, pg_ln2, mu_prior, pg_bh, lr);

    // iteration 2: fork bm on s1 || W1 on s0
    cudaEventRecord(ev[6], s0);
    cudaStreamWaitEvent(s1, ev[6], 0);
    launch_gh(s1, ph_bm, ph_hh, pg_bh, nullptr, N_, K_, N_, N_, K_, K_,
              (long long)NN_, 0, (long long)N_ * K_, 0, (long long)N_ * K_, 0,
              1, B_, 1, 0, 1);
    cudaEventRecord(ev[7], s1);
    launch_gh(s0, ph_hh, ph_W1T, nullptr, ph_hid, BN_, HID_, K_, K_, K_, HID_,
              0,0,0,0,0,0, 1, 1, 0, 1, 0, bh1);
    cudaStreamWaitEvent(s0, ev[7], 0);
    launch_gh(s0, ph_hid, ph_W2T, out, nullptr, BN_, K_, HID_, HID_, HID_, K_,
              0,0,0,0,0,0, 1, 1, 0, 3, 0, bh2, pg_h, mu_prior, pg_bh, lr, pg_res, pg_ln2);
}